// round 14
// baseline (speedup 1.0000x reference)
#include <cuda_runtime.h>
#include <cuda_fp16.h>
#include <math.h>

#define TT 2048

// Fragment-ordered plain-fp16 K and V(transposed):
// [blk][nt][p][lane] -> int4 {b0(2p),b1(2p),b0(2p+1),b1(2p+1)} (fp16x2 each)
__device__ int4 g_K[32 * 8 * 2 * 32];   // 256 KB
__device__ int4 g_V[32 * 8 * 2 * 32];   // 256 KB

__device__ __forceinline__ unsigned h2u(float x, float y) {
    __half2 h = __floats2half2_rn(x, y);
    return *(unsigned*)&h;
}

__global__ void __launch_bounds__(256) pack_kernel(
    const float* __restrict__ K, const float* __restrict__ V)
{
    const int i    = blockIdx.x * 256 + threadIdx.x;   // 0..16383
    const int lane = i & 31;
    const int p    = (i >> 5) & 1;
    const int nt   = (i >> 6) & 7;
    const int blk  = i >> 9;
    const int gid  = lane >> 2, qid = lane & 3;
    const int r    = 8 * nt + gid;
    const int c0   = 32 * p + 2 * qid;
    const int c1   = c0 + 16;

    const float* Kb = K + blk * 4096;
    const float* Vb = V + blk * 4096;

    g_K[i] = make_int4(
        (int)h2u(Kb[r * 64 + c0],      Kb[r * 64 + c0 + 1]),
        (int)h2u(Kb[r * 64 + c0 + 8],  Kb[r * 64 + c0 + 9]),
        (int)h2u(Kb[r * 64 + c1],      Kb[r * 64 + c1 + 1]),
        (int)h2u(Kb[r * 64 + c1 + 8],  Kb[r * 64 + c1 + 9]));

    g_V[i] = make_int4(
        (int)h2u(Vb[c0 * 64 + r],       Vb[(c0 + 1) * 64 + r]),
        (int)h2u(Vb[(c0 + 8) * 64 + r], Vb[(c0 + 9) * 64 + r]),
        (int)h2u(Vb[c1 * 64 + r],       Vb[(c1 + 1) * 64 + r]),
        (int)h2u(Vb[(c1 + 8) * 64 + r], Vb[(c1 + 9) * 64 + r]));
}

__device__ __forceinline__ void mma16(float c[4], const int4 a, int b0, int b1) {
    asm volatile(
        "mma.sync.aligned.m16n8k16.row.col.f32.f16.f16.f32 "
        "{%0,%1,%2,%3}, {%4,%5,%6,%7}, {%8,%9}, {%0,%1,%2,%3};\n"
        : "+f"(c[0]), "+f"(c[1]), "+f"(c[2]), "+f"(c[3])
        : "r"(a.x), "r"(a.y), "r"(a.z), "r"(a.w), "r"(b0), "r"(b1));
}

__device__ __forceinline__ void cp16(int4* smem_dst, const int4* gmem_src) {
    unsigned sa = (unsigned)__cvta_generic_to_shared(smem_dst);
    asm volatile("cp.async.cg.shared.global [%0], [%1], 16;\n"
                 :: "r"(sa), "l"(gmem_src));
}
#define CP_COMMIT() asm volatile("cp.async.commit_group;\n" ::: "memory")
#define CP_WAIT2()  asm volatile("cp.async.wait_group 2;\n" ::: "memory")

#define ONES 0x3C003C00   // fp16x2 (1.0, 1.0)

__device__ __forceinline__ int p3(int x) { return (x >= 3) ? x - 3 : x; }

// R14 = R10 (one CTA per token, split-KV 2 warps, causal block skipping,
// cp.async 3-slot K ring, early V LDGs, lazy-ref softmax, l via ones-MMA)
// with SMEM shrunk below the 9-CTA threshold: the O merge buffer is removed
// (warp 0 stages its alpha-scaled partial in Out itself; __syncthreads
// makes the global writes CTA-visible) and __launch_bounds__(64,9) lets
// ptxas shave ~15 regs without spill pressure.
__global__ void __launch_bounds__(64, 9) nsa14(
    const float* __restrict__ Q,   // [T,16,64]
    const int*   __restrict__ BI,  // [T,16]
    float* __restrict__ Out)       // [T,16,64]
{
    __shared__ int4  sK[2 * 3 * 256];    // 2 warps x 3 slots x 4KB = 24KB
    __shared__ float sm_m[2][16];
    __shared__ float sm_l[2][16];
    #define KSLOT(wi, si, ei) sK[(wi) * 768 + (si) * 256 + (ei)]

    const int t    = blockIdx.x;
    const int w    = threadIdx.x >> 5;
    const int lane = threadIdx.x & 31;
    const int gid  = lane >> 2;
    const int qid  = lane & 3;
    const int pb   = t >> 6;             // the (only possible) partial block

    // ---- Q A-fragments (scaled by 0.125*log2e), plain fp16, in regs -------
    int4 Qh[4];
    {
        const float SC = 0.18033688011112042f;   // 0.125 * log2(e)
        const float* Qp = Q + t * 1024;
        #pragma unroll
        for (int ks = 0; ks < 4; ++ks) {
            const int c0 = 16 * ks + 2 * qid;
            float2 x0 = *(const float2*)(Qp + gid * 64 + c0);
            float2 x1 = *(const float2*)(Qp + (gid + 8) * 64 + c0);
            float2 x2 = *(const float2*)(Qp + gid * 64 + c0 + 8);
            float2 x3 = *(const float2*)(Qp + (gid + 8) * 64 + c0 + 8);
            Qh[ks] = make_int4(
                (int)h2u(x0.x * SC, x0.y * SC),
                (int)h2u(x1.x * SC, x1.y * SC),
                (int)h2u(x2.x * SC, x2.y * SC),
                (int)h2u(x3.x * SC, x3.y * SC));
        }
    }

    float o[8][4];
    #pragma unroll
    for (int dt = 0; dt < 8; ++dt)
        o[dt][0] = o[dt][1] = o[dt][2] = o[dt][3] = 0.f;
    float la[4] = {0.f, 0.f, 0.f, 0.f};
    float m0 = -INFINITY, m1 = -INFINITY;
    float ref0 = 0.f, ref1 = 0.f;

    // ---- compact causally-valid block list --------------------------------
    const int* bip = BI + t * 16 + w * 8;
    int lst[8];
    int cnt = 0;
    #pragma unroll
    for (int s = 0; s < 8; ++s) {
        const int b = __ldg(bip + s);
        if (b <= pb) lst[cnt++] = b;     // b*64 <= t  <=>  b <= t>>6
    }

    if (cnt > 0) {
        // ---- preload: (lst0, half0) -> slot0, (lst0, half1) -> slot1 ------
        {
            const int4* srcb = g_K + (size_t)lst[0] * 512;
            #pragma unroll
            for (int j = 0; j < 8; ++j)
                cp16(&KSLOT(w, 0, j * 32 + lane), srcb + j * 32 + lane);
            CP_COMMIT();
            #pragma unroll
            for (int j = 0; j < 8; ++j)
                cp16(&KSLOT(w, 1, j * 32 + lane), srcb + 256 + j * 32 + lane);
            CP_COMMIT();
        }

        int cslot = 0;

        #pragma unroll 1
        for (int i = 0; i < cnt; ++i) {
            const int blkc = lst[i];
            const int nxt  = (i + 1 < cnt) ? lst[i + 1] : 0;
            const bool domask = (blkc == pb);
            const int4* Vb = g_V + (size_t)blkc * 512;
            const int4* Kn = g_K + (size_t)nxt * 512;

            float bm0 = m0, bm1 = m1;
            int4 Ph[2];

            #pragma unroll
            for (int h = 0; h < 2; ++h) {
                // -- issue next block's same-half K into slot cslot+2 -------
                {
                    const int4* src = Kn + h * 256;
                    const int tslot = p3(cslot + 2);
                    #pragma unroll
                    for (int j = 0; j < 8; ++j)
                        cp16(&KSLOT(w, tslot, j * 32 + lane), src + j * 32 + lane);
                    CP_COMMIT();
                }
                // -- early V loads for this half ----------------------------
                int4 v[8];
                #pragma unroll
                for (int dt = 0; dt < 8; ++dt)
                    v[dt] = Vb[dt * 64 + 32 * h + lane];

                // -- wait for this half's K, then QK ------------------------
                CP_WAIT2();
                float sc[4][4];
                #pragma unroll
                for (int nt = 0; nt < 4; ++nt) {
                    const int4 ba = KSLOT(w, cslot, nt * 64 + lane);
                    const int4 bb = KSLOT(w, cslot, nt * 64 + 32 + lane);
                    float a[4] = {0.f, 0.f, 0.f, 0.f};
                    mma16(a, Qh[0], ba.x, ba.y);
                    mma16(a, Qh[1], ba.z, ba.w);
                    mma16(a, Qh[2], bb.x, bb.y);
                    mma16(a, Qh[3], bb.z, bb.w);
                    sc[nt][0] = a[0]; sc[nt][1] = a[1];
                    sc[nt][2] = a[2]; sc[nt][3] = a[3];
                }
                if (domask) {   // warp-uniform: only the boundary block
                    #pragma unroll
                    for (int nt = 0; nt < 4; ++nt) {
                        const int kp = blkc * 64 + 8 * (nt + 4 * h) + 2 * qid;
                        if (kp     > t) { sc[nt][0] = -INFINITY; sc[nt][2] = -INFINITY; }
                        if (kp + 1 > t) { sc[nt][1] = -INFINITY; sc[nt][3] = -INFINITY; }
                    }
                }
                #pragma unroll
                for (int nt = 0; nt < 4; ++nt) {
                    bm0 = fmaxf(bm0, fmaxf(sc[nt][0], sc[nt][1]));
                    bm1 = fmaxf(bm1, fmaxf(sc[nt][2], sc[nt][3]));
                }
                // -- exp (lazy reference) -> P A-fragments ------------------
                #pragma unroll
                for (int p = 0; p < 2; ++p) {
                    unsigned hb[4];
                    #pragma unroll
                    for (int j = 0; j < 2; ++j) {
                        const int nt = 2 * p + j;
                        __half2 e01 = h2exp2(__floats2half2_rn(sc[nt][0] - ref0,
                                                               sc[nt][1] - ref0));
                        __half2 e23 = h2exp2(__floats2half2_rn(sc[nt][2] - ref1,
                                                               sc[nt][3] - ref1));
                        hb[2 * j]     = *(unsigned*)&e01;
                        hb[2 * j + 1] = *(unsigned*)&e23;
                    }
                    Ph[p] = make_int4((int)hb[0], (int)hb[1], (int)hb[2], (int)hb[3]);
                }
                // -- PV over this half's k-steps ----------------------------
                #pragma unroll
                for (int dt = 0; dt < 8; ++dt) {
                    mma16(o[dt], Ph[0], v[dt].x, v[dt].y);
                    mma16(o[dt], Ph[1], v[dt].z, v[dt].w);
                }
                mma16(la, Ph[0], ONES, ONES);
                mma16(la, Ph[1], ONES, ONES);

                cslot = p3(cslot + 1);
            }

            // ---- block end: update max / reference, rescale ---------------
            bm0 = fmaxf(bm0, __shfl_xor_sync(0xffffffffu, bm0, 1));
            bm0 = fmaxf(bm0, __shfl_xor_sync(0xffffffffu, bm0, 2));
            bm1 = fmaxf(bm1, __shfl_xor_sync(0xffffffffu, bm1, 1));
            bm1 = fmaxf(bm1, __shfl_xor_sync(0xffffffffu, bm1, 2));
            const float nr0 = (bm0 == -INFINITY) ? 0.f : bm0;
            const float nr1 = (bm1 == -INFINITY) ? 0.f : bm1;
            const float cr0 = exp2f(ref0 - nr0);
            const float cr1 = exp2f(ref1 - nr1);
            #pragma unroll
            for (int dt = 0; dt < 8; ++dt) {
                o[dt][0] *= cr0; o[dt][1] *= cr0;
                o[dt][2] *= cr1; o[dt][3] *= cr1;
            }
            la[0] *= cr0; la[1] *= cr0; la[2] *= cr1; la[3] *= cr1;
            m0 = bm0; m1 = bm1; ref0 = nr0; ref1 = nr1;
        }
    }

    // ---- split-softmax merge (O staged through Out itself) ----------------
    if (qid == 0) {
        sm_m[w][gid] = m0;  sm_m[w][gid + 8] = m1;
        sm_l[w][gid] = la[0]; sm_l[w][gid + 8] = la[2];
    }
    __syncthreads();

    const float M0 = fmaxf(sm_m[0][gid],     sm_m[1][gid]);   // finite (w0 has blk 0)
    const float M1 = fmaxf(sm_m[0][gid + 8], sm_m[1][gid + 8]);
    const float a0 = exp2f(ref0 - M0);
    const float a1 = exp2f(ref1 - M1);

    float* ob = Out + t * 1024;
    if (w == 0) {
        #pragma unroll
        for (int dt = 0; dt < 8; ++dt) {
            *(float2*)(ob + gid * 64 + 8 * dt + 2 * qid) =
                make_float2(o[dt][0] * a0, o[dt][1] * a0);
            *(float2*)(ob + (gid + 8) * 64 + 8 * dt + 2 * qid) =
                make_float2(o[dt][2] * a1, o[dt][3] * a1);
        }
    }
    __syncthreads();    // global writes by warp 0 visible CTA-wide
    if (w == 1) {
        const float rf00 = (sm_m[0][gid] == -INFINITY)     ? 0.f : sm_m[0][gid];
        const float rf10 = (sm_m[1][gid] == -INFINITY)     ? 0.f : sm_m[1][gid];
        const float rf01 = (sm_m[0][gid + 8] == -INFINITY) ? 0.f : sm_m[0][gid + 8];
        const float rf11 = (sm_m[1][gid + 8] == -INFINITY) ? 0.f : sm_m[1][gid + 8];
        const float L0 = exp2f(rf00 - M0) * sm_l[0][gid]
                       + exp2f(rf10 - M0) * sm_l[1][gid];
        const float L1 = exp2f(rf01 - M1) * sm_l[0][gid + 8]
                       + exp2f(rf11 - M1) * sm_l[1][gid + 8];
        const float i0 = 1.f / L0;
        const float i1 = 1.f / L1;
        #pragma unroll
        for (int dt = 0; dt < 8; ++dt) {
            float2 u0 = *(float2*)(ob + gid * 64 + 8 * dt + 2 * qid);
            float2 u1 = *(float2*)(ob + (gid + 8) * 64 + 8 * dt + 2 * qid);
            *(float2*)(ob + gid * 64 + 8 * dt + 2 * qid) =
                make_float2((u0.x + o[dt][0] * a0) * i0,
                            (u0.y + o[dt][1] * a0) * i0);
            *(float2*)(ob + (gid + 8) * 64 + 8 * dt + 2 * qid) =
                make_float2((u1.x + o[dt][2] * a1) * i1,
                            (u1.y + o[dt][3] * a1) * i1);
        }
    }
}

extern "C" void kernel_launch(void* const* d_in, const int* in_sizes, int n_in,
                              void* d_out, int out_size) {
    const float* Q  = (const float*)d_in[0];
    const float* K  = (const float*)d_in[1];
    const float* V  = (const float*)d_in[2];
    const int*   BI = (const int*)d_in[3];
    pack_kernel<<<64, 256>>>(K, V);
    nsa14<<<TT, 64>>>(Q, BI, (float*)d_out);
}

// round 15
// speedup vs baseline: 1.9082x; 1.9082x over previous
#include <cuda_runtime.h>
#include <cuda_fp16.h>
#include <math.h>

#define TT 2048

// Fragment-ordered plain-fp16 K and V(transposed):
// [blk][nt][p][lane] -> int4 {b0(2p),b1(2p),b0(2p+1),b1(2p+1)} (fp16x2 each)
__device__ int4 g_K[32 * 8 * 2 * 32];   // 256 KB
__device__ int4 g_V[32 * 8 * 2 * 32];   // 256 KB

__device__ __forceinline__ unsigned h2u(float x, float y) {
    __half2 h = __floats2half2_rn(x, y);
    return *(unsigned*)&h;
}

__global__ void __launch_bounds__(256) pack_kernel(
    const float* __restrict__ K, const float* __restrict__ V)
{
    const int i    = blockIdx.x * 256 + threadIdx.x;   // 0..16383
    const int lane = i & 31;
    const int p    = (i >> 5) & 1;
    const int nt   = (i >> 6) & 7;
    const int blk  = i >> 9;
    const int gid  = lane >> 2, qid = lane & 3;
    const int r    = 8 * nt + gid;
    const int c0   = 32 * p + 2 * qid;
    const int c1   = c0 + 16;

    const float* Kb = K + blk * 4096;
    const float* Vb = V + blk * 4096;

    g_K[i] = make_int4(
        (int)h2u(Kb[r * 64 + c0],      Kb[r * 64 + c0 + 1]),
        (int)h2u(Kb[r * 64 + c0 + 8],  Kb[r * 64 + c0 + 9]),
        (int)h2u(Kb[r * 64 + c1],      Kb[r * 64 + c1 + 1]),
        (int)h2u(Kb[r * 64 + c1 + 8],  Kb[r * 64 + c1 + 9]));

    g_V[i] = make_int4(
        (int)h2u(Vb[c0 * 64 + r],       Vb[(c0 + 1) * 64 + r]),
        (int)h2u(Vb[(c0 + 8) * 64 + r], Vb[(c0 + 9) * 64 + r]),
        (int)h2u(Vb[c1 * 64 + r],       Vb[(c1 + 1) * 64 + r]),
        (int)h2u(Vb[(c1 + 8) * 64 + r], Vb[(c1 + 9) * 64 + r]));
}

__device__ __forceinline__ void mma16(float c[4], const int4 a, int b0, int b1) {
    asm volatile(
        "mma.sync.aligned.m16n8k16.row.col.f32.f16.f16.f32 "
        "{%0,%1,%2,%3}, {%4,%5,%6,%7}, {%8,%9}, {%0,%1,%2,%3};\n"
        : "+f"(c[0]), "+f"(c[1]), "+f"(c[2]), "+f"(c[3])
        : "r"(a.x), "r"(a.y), "r"(a.z), "r"(a.w), "r"(b0), "r"(b1));
}

// L1-cacheable async copy: K blocks are shared across many co-resident
// warps/CTAs on the same SM -> .ca turns repeat fetches into L1 hits.
__device__ __forceinline__ void cp16(int4* smem_dst, const int4* gmem_src) {
    unsigned sa = (unsigned)__cvta_generic_to_shared(smem_dst);
    asm volatile("cp.async.ca.shared.global [%0], [%1], 16;\n"
                 :: "r"(sa), "l"(gmem_src));
}
#define CP_COMMIT() asm volatile("cp.async.commit_group;\n" ::: "memory")
#define CP_WAIT2()  asm volatile("cp.async.wait_group 2;\n" ::: "memory")
#define CP_WAIT0()  asm volatile("cp.async.wait_group 0;\n" ::: "memory")

#define ONES 0x3C003C00   // fp16x2 (1.0, 1.0)

__device__ __forceinline__ int p3(int x) { return (x >= 3) ? x - 3 : x; }

// R15 = R10 (one CTA per token, split-KV 2 warps, causal block skipping,
// cp.async 3-slot K ring 2 halves ahead, early V LDGs, lazy-ref softmax,
// l via ones-MMA, split-softmax merge) with two traffic cuts:
//  - cp.async uses .ca (L1-cacheable) instead of .cg
//  - the last block issues NO tail prefetch; it drains with wait_group 0
__global__ void __launch_bounds__(64, 8) nsa15(
    const float* __restrict__ Q,   // [T,16,64]
    const int*   __restrict__ BI,  // [T,16]
    float* __restrict__ Out)       // [T,16,64]
{
    __shared__ int4  sK[2 * 3 * 256];    // 2 warps x 3 slots x 4KB
    __shared__ float sm_m[2][16];
    __shared__ float sm_l[2][16];
    __shared__ float sm_o[16 * 66];
    #define KSLOT(wi, si, ei) sK[(wi) * 768 + (si) * 256 + (ei)]

    const int t    = blockIdx.x;
    const int w    = threadIdx.x >> 5;
    const int lane = threadIdx.x & 31;
    const int gid  = lane >> 2;
    const int qid  = lane & 3;
    const int pb   = t >> 6;             // the (only possible) partial block

    // ---- Q A-fragments (scaled by 0.125*log2e), plain fp16, in regs -------
    int4 Qh[4];
    {
        const float SC = 0.18033688011112042f;   // 0.125 * log2(e)
        const float* Qp = Q + t * 1024;
        #pragma unroll
        for (int ks = 0; ks < 4; ++ks) {
            const int c0 = 16 * ks + 2 * qid;
            float2 x0 = *(const float2*)(Qp + gid * 64 + c0);
            float2 x1 = *(const float2*)(Qp + (gid + 8) * 64 + c0);
            float2 x2 = *(const float2*)(Qp + gid * 64 + c0 + 8);
            float2 x3 = *(const float2*)(Qp + (gid + 8) * 64 + c0 + 8);
            Qh[ks] = make_int4(
                (int)h2u(x0.x * SC, x0.y * SC),
                (int)h2u(x1.x * SC, x1.y * SC),
                (int)h2u(x2.x * SC, x2.y * SC),
                (int)h2u(x3.x * SC, x3.y * SC));
        }
    }

    float o[8][4];
    #pragma unroll
    for (int dt = 0; dt < 8; ++dt)
        o[dt][0] = o[dt][1] = o[dt][2] = o[dt][3] = 0.f;
    float la[4] = {0.f, 0.f, 0.f, 0.f};
    float m0 = -INFINITY, m1 = -INFINITY;
    float ref0 = 0.f, ref1 = 0.f;

    // ---- compact causally-valid block list --------------------------------
    const int* bip = BI + t * 16 + w * 8;
    int lst[8];
    int cnt = 0;
    #pragma unroll
    for (int s = 0; s < 8; ++s) {
        const int b = __ldg(bip + s);
        if (b <= pb) lst[cnt++] = b;     // b*64 <= t  <=>  b <= t>>6
    }

    if (cnt > 0) {
        // ---- preload: (lst0, half0) -> slot0, (lst0, half1) -> slot1 ------
        {
            const int4* srcb = g_K + (size_t)lst[0] * 512;
            #pragma unroll
            for (int j = 0; j < 8; ++j)
                cp16(&KSLOT(w, 0, j * 32 + lane), srcb + j * 32 + lane);
            CP_COMMIT();
            #pragma unroll
            for (int j = 0; j < 8; ++j)
                cp16(&KSLOT(w, 1, j * 32 + lane), srcb + 256 + j * 32 + lane);
            CP_COMMIT();
        }

        int cslot = 0;

        #pragma unroll 1
        for (int i = 0; i < cnt; ++i) {
            const int blkc = lst[i];
            const bool has_next = (i + 1 < cnt);
            const int nxt  = has_next ? lst[i + 1] : 0;
            const bool domask = (blkc == pb);
            const int4* Vb = g_V + (size_t)blkc * 512;
            const int4* Kn = g_K + (size_t)nxt * 512;

            float bm0 = m0, bm1 = m1;
            int4 Ph[2];

            #pragma unroll
            for (int h = 0; h < 2; ++h) {
                // -- prefetch next block's same-half K (skip on last block) -
                if (has_next) {
                    const int4* src = Kn + h * 256;
                    const int tslot = p3(cslot + 2);
                    #pragma unroll
                    for (int j = 0; j < 8; ++j)
                        cp16(&KSLOT(w, tslot, j * 32 + lane), src + j * 32 + lane);
                    CP_COMMIT();
                }
                // -- early V loads for this half ----------------------------
                int4 v[8];
                #pragma unroll
                for (int dt = 0; dt < 8; ++dt)
                    v[dt] = Vb[dt * 64 + 32 * h + lane];

                // -- wait for this half's K, then QK ------------------------
                if (has_next) { CP_WAIT2(); } else { CP_WAIT0(); }
                float sc[4][4];
                #pragma unroll
                for (int nt = 0; nt < 4; ++nt) {
                    const int4 ba = KSLOT(w, cslot, nt * 64 + lane);
                    const int4 bb = KSLOT(w, cslot, nt * 64 + 32 + lane);
                    float a[4] = {0.f, 0.f, 0.f, 0.f};
                    mma16(a, Qh[0], ba.x, ba.y);
                    mma16(a, Qh[1], ba.z, ba.w);
                    mma16(a, Qh[2], bb.x, bb.y);
                    mma16(a, Qh[3], bb.z, bb.w);
                    sc[nt][0] = a[0]; sc[nt][1] = a[1];
                    sc[nt][2] = a[2]; sc[nt][3] = a[3];
                }
                if (domask) {   // warp-uniform: only the boundary block
                    #pragma unroll
                    for (int nt = 0; nt < 4; ++nt) {
                        const int kp = blkc * 64 + 8 * (nt + 4 * h) + 2 * qid;
                        if (kp     > t) { sc[nt][0] = -INFINITY; sc[nt][2] = -INFINITY; }
                        if (kp + 1 > t) { sc[nt][1] = -INFINITY; sc[nt][3] = -INFINITY; }
                    }
                }
                #pragma unroll
                for (int nt = 0; nt < 4; ++nt) {
                    bm0 = fmaxf(bm0, fmaxf(sc[nt][0], sc[nt][1]));
                    bm1 = fmaxf(bm1, fmaxf(sc[nt][2], sc[nt][3]));
                }
                // -- exp (lazy reference) -> P A-fragments ------------------
                #pragma unroll
                for (int p = 0; p < 2; ++p) {
                    unsigned hb[4];
                    #pragma unroll
                    for (int j = 0; j < 2; ++j) {
                        const int nt = 2 * p + j;
                        __half2 e01 = h2exp2(__floats2half2_rn(sc[nt][0] - ref0,
                                                               sc[nt][1] - ref0));
                        __half2 e23 = h2exp2(__floats2half2_rn(sc[nt][2] - ref1,
                                                               sc[nt][3] - ref1));
                        hb[2 * j]     = *(unsigned*)&e01;
                        hb[2 * j + 1] = *(unsigned*)&e23;
                    }
                    Ph[p] = make_int4((int)hb[0], (int)hb[1], (int)hb[2], (int)hb[3]);
                }
                // -- PV over this half's k-steps ----------------------------
                #pragma unroll
                for (int dt = 0; dt < 8; ++dt) {
                    mma16(o[dt], Ph[0], v[dt].x, v[dt].y);
                    mma16(o[dt], Ph[1], v[dt].z, v[dt].w);
                }
                mma16(la, Ph[0], ONES, ONES);
                mma16(la, Ph[1], ONES, ONES);

                cslot = p3(cslot + 1);
            }

            // ---- block end: update max / reference, rescale ---------------
            bm0 = fmaxf(bm0, __shfl_xor_sync(0xffffffffu, bm0, 1));
            bm0 = fmaxf(bm0, __shfl_xor_sync(0xffffffffu, bm0, 2));
            bm1 = fmaxf(bm1, __shfl_xor_sync(0xffffffffu, bm1, 1));
            bm1 = fmaxf(bm1, __shfl_xor_sync(0xffffffffu, bm1, 2));
            const float nr0 = (bm0 == -INFINITY) ? 0.f : bm0;
            const float nr1 = (bm1 == -INFINITY) ? 0.f : bm1;
            const float cr0 = exp2f(ref0 - nr0);
            const float cr1 = exp2f(ref1 - nr1);
            #pragma unroll
            for (int dt = 0; dt < 8; ++dt) {
                o[dt][0] *= cr0; o[dt][1] *= cr0;
                o[dt][2] *= cr1; o[dt][3] *= cr1;
            }
            la[0] *= cr0; la[1] *= cr0; la[2] *= cr1; la[3] *= cr1;
            m0 = bm0; m1 = bm1; ref0 = nr0; ref1 = nr1;
        }
    }

    // ---- split-softmax merge ----------------------------------------------
    if (qid == 0) {
        sm_m[w][gid] = m0;  sm_m[w][gid + 8] = m1;
        sm_l[w][gid] = la[0]; sm_l[w][gid + 8] = la[2];
    }
    __syncthreads();

    const float M0 = fmaxf(sm_m[0][gid],     sm_m[1][gid]);   // finite (w0 has blk 0)
    const float M1 = fmaxf(sm_m[0][gid + 8], sm_m[1][gid + 8]);
    const float a0 = exp2f(ref0 - M0);
    const float a1 = exp2f(ref1 - M1);

    if (w == 0) {
        #pragma unroll
        for (int dt = 0; dt < 8; ++dt) {
            *(float2*)(sm_o + gid * 66 + 8 * dt + 2 * qid) =
                make_float2(o[dt][0] * a0, o[dt][1] * a0);
            *(float2*)(sm_o + (gid + 8) * 66 + 8 * dt + 2 * qid) =
                make_float2(o[dt][2] * a1, o[dt][3] * a1);
        }
    }
    __syncthreads();
    if (w == 1) {
        const float rf00 = (sm_m[0][gid] == -INFINITY)     ? 0.f : sm_m[0][gid];
        const float rf10 = (sm_m[1][gid] == -INFINITY)     ? 0.f : sm_m[1][gid];
        const float rf01 = (sm_m[0][gid + 8] == -INFINITY) ? 0.f : sm_m[0][gid + 8];
        const float rf11 = (sm_m[1][gid + 8] == -INFINITY) ? 0.f : sm_m[1][gid + 8];
        const float L0 = exp2f(rf00 - M0) * sm_l[0][gid]
                       + exp2f(rf10 - M0) * sm_l[1][gid];
        const float L1 = exp2f(rf01 - M1) * sm_l[0][gid + 8]
                       + exp2f(rf11 - M1) * sm_l[1][gid + 8];
        const float i0 = 1.f / L0;
        const float i1 = 1.f / L1;
        float* ob = Out + t * 1024;
        #pragma unroll
        for (int dt = 0; dt < 8; ++dt) {
            float2 u0 = *(float2*)(sm_o + gid * 66 + 8 * dt + 2 * qid);
            float2 u1 = *(float2*)(sm_o + (gid + 8) * 66 + 8 * dt + 2 * qid);
            *(float2*)(ob + gid * 64 + 8 * dt + 2 * qid) =
                make_float2((u0.x + o[dt][0] * a0) * i0,
                            (u0.y + o[dt][1] * a0) * i0);
            *(float2*)(ob + (gid + 8) * 64 + 8 * dt + 2 * qid) =
                make_float2((u1.x + o[dt][2] * a1) * i1,
                            (u1.y + o[dt][3] * a1) * i1);
        }
    }
}

extern "C" void kernel_launch(void* const* d_in, const int* in_sizes, int n_in,
                              void* d_out, int out_size) {
    const float* Q  = (const float*)d_in[0];
    const float* K  = (const float*)d_in[1];
    const float* V  = (const float*)d_in[2];
    const int*   BI = (const int*)d_in[3];
    pack_kernel<<<64, 256>>>(K, V);
    nsa15<<<TT, 64>>>(Q, BI, (float*)d_out);
}

// round 16
// speedup vs baseline: 2.0156x; 1.0563x over previous
#include <cuda_runtime.h>
#include <cuda_fp16.h>
#include <math.h>

#define TT 2048

// Fragment-ordered plain-fp16 K and V(transposed):
// [blk][nt][p][lane] -> int4 {b0(2p),b1(2p),b0(2p+1),b1(2p+1)} (fp16x2 each)
__device__ int4 g_K[32 * 8 * 2 * 32];   // 256 KB
__device__ int4 g_V[32 * 8 * 2 * 32];   // 256 KB

__device__ __forceinline__ unsigned h2u(float x, float y) {
    __half2 h = __floats2half2_rn(x, y);
    return *(unsigned*)&h;
}

__global__ void __launch_bounds__(256) pack_kernel(
    const float* __restrict__ K, const float* __restrict__ V)
{
    const int i    = blockIdx.x * 256 + threadIdx.x;   // 0..16383
    const int lane = i & 31;
    const int p    = (i >> 5) & 1;
    const int nt   = (i >> 6) & 7;
    const int blk  = i >> 9;
    const int gid  = lane >> 2, qid = lane & 3;
    const int r    = 8 * nt + gid;
    const int c0   = 32 * p + 2 * qid;
    const int c1   = c0 + 16;

    const float* Kb = K + blk * 4096;
    const float* Vb = V + blk * 4096;

    g_K[i] = make_int4(
        (int)h2u(Kb[r * 64 + c0],      Kb[r * 64 + c0 + 1]),
        (int)h2u(Kb[r * 64 + c0 + 8],  Kb[r * 64 + c0 + 9]),
        (int)h2u(Kb[r * 64 + c1],      Kb[r * 64 + c1 + 1]),
        (int)h2u(Kb[r * 64 + c1 + 8],  Kb[r * 64 + c1 + 9]));

    g_V[i] = make_int4(
        (int)h2u(Vb[c0 * 64 + r],       Vb[(c0 + 1) * 64 + r]),
        (int)h2u(Vb[(c0 + 8) * 64 + r], Vb[(c0 + 9) * 64 + r]),
        (int)h2u(Vb[c1 * 64 + r],       Vb[(c1 + 1) * 64 + r]),
        (int)h2u(Vb[(c1 + 8) * 64 + r], Vb[(c1 + 9) * 64 + r]));
}

__device__ __forceinline__ void mma16(float c[4], const int4 a, int b0, int b1) {
    asm volatile(
        "mma.sync.aligned.m16n8k16.row.col.f32.f16.f16.f32 "
        "{%0,%1,%2,%3}, {%4,%5,%6,%7}, {%8,%9}, {%0,%1,%2,%3};\n"
        : "+f"(c[0]), "+f"(c[1]), "+f"(c[2]), "+f"(c[3])
        : "r"(a.x), "r"(a.y), "r"(a.z), "r"(a.w), "r"(b0), "r"(b1));
}

__device__ __forceinline__ void cp16(int4* smem_dst, const int4* gmem_src) {
    unsigned sa = (unsigned)__cvta_generic_to_shared(smem_dst);
    asm volatile("cp.async.cg.shared.global [%0], [%1], 16;\n"
                 :: "r"(sa), "l"(gmem_src));
}
#define CP_COMMIT() asm volatile("cp.async.commit_group;\n" ::: "memory")
#define CP_WAIT2()  asm volatile("cp.async.wait_group 2;\n" ::: "memory")

#define ONES 0x3C003C00   // fp16x2 (1.0, 1.0)

__device__ __forceinline__ int p3(int x) { return (x >= 3) ? x - 3 : x; }

// R16 = R10 mainloop verbatim (one CTA per token, split-KV 2 warps, causal
// block skipping, cp.async.cg 3-slot K ring 2 halves ahead, early V LDGs,
// lazy-ref softmax, l via ones-MMA) with ONE change: the 4.2KB SMEM O-merge
// buffer is removed (warp 0 stages its alpha-scaled partial in Out itself).
// SMEM 29KB -> 24.8KB lifts residency from 7 to the RF-exact 8 CTAs/SM.
__global__ void __launch_bounds__(64, 8) nsa16(
    const float* __restrict__ Q,   // [T,16,64]
    const int*   __restrict__ BI,  // [T,16]
    float* __restrict__ Out)       // [T,16,64]
{
    __shared__ int4  sK[2 * 3 * 256];    // 2 warps x 3 slots x 4KB = 24KB
    __shared__ float sm_m[2][16];
    __shared__ float sm_l[2][16];
    #define KSLOT(wi, si, ei) sK[(wi) * 768 + (si) * 256 + (ei)]

    const int t    = blockIdx.x;
    const int w    = threadIdx.x >> 5;
    const int lane = threadIdx.x & 31;
    const int gid  = lane >> 2;
    const int qid  = lane & 3;
    const int pb   = t >> 6;             // the (only possible) partial block

    // ---- Q A-fragments (scaled by 0.125*log2e), plain fp16, in regs -------
    int4 Qh[4];
    {
        const float SC = 0.18033688011112042f;   // 0.125 * log2(e)
        const float* Qp = Q + t * 1024;
        #pragma unroll
        for (int ks = 0; ks < 4; ++ks) {
            const int c0 = 16 * ks + 2 * qid;
            float2 x0 = *(const float2*)(Qp + gid * 64 + c0);
            float2 x1 = *(const float2*)(Qp + (gid + 8) * 64 + c0);
            float2 x2 = *(const float2*)(Qp + gid * 64 + c0 + 8);
            float2 x3 = *(const float2*)(Qp + (gid + 8) * 64 + c0 + 8);
            Qh[ks] = make_int4(
                (int)h2u(x0.x * SC, x0.y * SC),
                (int)h2u(x1.x * SC, x1.y * SC),
                (int)h2u(x2.x * SC, x2.y * SC),
                (int)h2u(x3.x * SC, x3.y * SC));
        }
    }

    float o[8][4];
    #pragma unroll
    for (int dt = 0; dt < 8; ++dt)
        o[dt][0] = o[dt][1] = o[dt][2] = o[dt][3] = 0.f;
    float la[4] = {0.f, 0.f, 0.f, 0.f};
    float m0 = -INFINITY, m1 = -INFINITY;
    float ref0 = 0.f, ref1 = 0.f;

    // ---- compact causally-valid block list --------------------------------
    const int* bip = BI + t * 16 + w * 8;
    int lst[8];
    int cnt = 0;
    #pragma unroll
    for (int s = 0; s < 8; ++s) {
        const int b = __ldg(bip + s);
        if (b <= pb) lst[cnt++] = b;     // b*64 <= t  <=>  b <= t>>6
    }

    if (cnt > 0) {
        // ---- preload: (lst0, half0) -> slot0, (lst0, half1) -> slot1 ------
        {
            const int4* srcb = g_K + (size_t)lst[0] * 512;
            #pragma unroll
            for (int j = 0; j < 8; ++j)
                cp16(&KSLOT(w, 0, j * 32 + lane), srcb + j * 32 + lane);
            CP_COMMIT();
            #pragma unroll
            for (int j = 0; j < 8; ++j)
                cp16(&KSLOT(w, 1, j * 32 + lane), srcb + 256 + j * 32 + lane);
            CP_COMMIT();
        }

        int cslot = 0;

        #pragma unroll 1
        for (int i = 0; i < cnt; ++i) {
            const int blkc = lst[i];
            const int nxt  = (i + 1 < cnt) ? lst[i + 1] : 0;
            const bool domask = (blkc == pb);
            const int4* Vb = g_V + (size_t)blkc * 512;
            const int4* Kn = g_K + (size_t)nxt * 512;

            float bm0 = m0, bm1 = m1;
            int4 Ph[2];

            #pragma unroll
            for (int h = 0; h < 2; ++h) {
                // -- issue next block's same-half K into slot cslot+2 -------
                {
                    const int4* src = Kn + h * 256;
                    const int tslot = p3(cslot + 2);
                    #pragma unroll
                    for (int j = 0; j < 8; ++j)
                        cp16(&KSLOT(w, tslot, j * 32 + lane), src + j * 32 + lane);
                    CP_COMMIT();
                }
                // -- early V loads for this half ----------------------------
                int4 v[8];
                #pragma unroll
                for (int dt = 0; dt < 8; ++dt)
                    v[dt] = Vb[dt * 64 + 32 * h + lane];

                // -- wait for this half's K, then QK ------------------------
                CP_WAIT2();
                float sc[4][4];
                #pragma unroll
                for (int nt = 0; nt < 4; ++nt) {
                    const int4 ba = KSLOT(w, cslot, nt * 64 + lane);
                    const int4 bb = KSLOT(w, cslot, nt * 64 + 32 + lane);
                    float a[4] = {0.f, 0.f, 0.f, 0.f};
                    mma16(a, Qh[0], ba.x, ba.y);
                    mma16(a, Qh[1], ba.z, ba.w);
                    mma16(a, Qh[2], bb.x, bb.y);
                    mma16(a, Qh[3], bb.z, bb.w);
                    sc[nt][0] = a[0]; sc[nt][1] = a[1];
                    sc[nt][2] = a[2]; sc[nt][3] = a[3];
                }
                if (domask) {   // warp-uniform: only the boundary block
                    #pragma unroll
                    for (int nt = 0; nt < 4; ++nt) {
                        const int kp = blkc * 64 + 8 * (nt + 4 * h) + 2 * qid;
                        if (kp     > t) { sc[nt][0] = -INFINITY; sc[nt][2] = -INFINITY; }
                        if (kp + 1 > t) { sc[nt][1] = -INFINITY; sc[nt][3] = -INFINITY; }
                    }
                }
                #pragma unroll
                for (int nt = 0; nt < 4; ++nt) {
                    bm0 = fmaxf(bm0, fmaxf(sc[nt][0], sc[nt][1]));
                    bm1 = fmaxf(bm1, fmaxf(sc[nt][2], sc[nt][3]));
                }
                // -- exp (lazy reference) -> P A-fragments ------------------
                #pragma unroll
                for (int p = 0; p < 2; ++p) {
                    unsigned hb[4];
                    #pragma unroll
                    for (int j = 0; j < 2; ++j) {
                        const int nt = 2 * p + j;
                        __half2 e01 = h2exp2(__floats2half2_rn(sc[nt][0] - ref0,
                                                               sc[nt][1] - ref0));
                        __half2 e23 = h2exp2(__floats2half2_rn(sc[nt][2] - ref1,
                                                               sc[nt][3] - ref1));
                        hb[2 * j]     = *(unsigned*)&e01;
                        hb[2 * j + 1] = *(unsigned*)&e23;
                    }
                    Ph[p] = make_int4((int)hb[0], (int)hb[1], (int)hb[2], (int)hb[3]);
                }
                // -- PV over this half's k-steps ----------------------------
                #pragma unroll
                for (int dt = 0; dt < 8; ++dt) {
                    mma16(o[dt], Ph[0], v[dt].x, v[dt].y);
                    mma16(o[dt], Ph[1], v[dt].z, v[dt].w);
                }
                mma16(la, Ph[0], ONES, ONES);
                mma16(la, Ph[1], ONES, ONES);

                cslot = p3(cslot + 1);
            }

            // ---- block end: update max / reference, rescale ---------------
            bm0 = fmaxf(bm0, __shfl_xor_sync(0xffffffffu, bm0, 1));
            bm0 = fmaxf(bm0, __shfl_xor_sync(0xffffffffu, bm0, 2));
            bm1 = fmaxf(bm1, __shfl_xor_sync(0xffffffffu, bm1, 1));
            bm1 = fmaxf(bm1, __shfl_xor_sync(0xffffffffu, bm1, 2));
            const float nr0 = (bm0 == -INFINITY) ? 0.f : bm0;
            const float nr1 = (bm1 == -INFINITY) ? 0.f : bm1;
            const float cr0 = exp2f(ref0 - nr0);
            const float cr1 = exp2f(ref1 - nr1);
            #pragma unroll
            for (int dt = 0; dt < 8; ++dt) {
                o[dt][0] *= cr0; o[dt][1] *= cr0;
                o[dt][2] *= cr1; o[dt][3] *= cr1;
            }
            la[0] *= cr0; la[1] *= cr0; la[2] *= cr1; la[3] *= cr1;
            m0 = bm0; m1 = bm1; ref0 = nr0; ref1 = nr1;
        }
    }

    // ---- split-softmax merge (O staged through Out itself) ----------------
    if (qid == 0) {
        sm_m[w][gid] = m0;  sm_m[w][gid + 8] = m1;
        sm_l[w][gid] = la[0]; sm_l[w][gid + 8] = la[2];
    }
    __syncthreads();

    const float M0 = fmaxf(sm_m[0][gid],     sm_m[1][gid]);   // finite (w0 has blk 0)
    const float M1 = fmaxf(sm_m[0][gid + 8], sm_m[1][gid + 8]);
    const float a0 = exp2f(ref0 - M0);
    const float a1 = exp2f(ref1 - M1);

    float* ob = Out + t * 1024;
    if (w == 0) {
        #pragma unroll
        for (int dt = 0; dt < 8; ++dt) {
            *(float2*)(ob + gid * 64 + 8 * dt + 2 * qid) =
                make_float2(o[dt][0] * a0, o[dt][1] * a0);
            *(float2*)(ob + (gid + 8) * 64 + 8 * dt + 2 * qid) =
                make_float2(o[dt][2] * a1, o[dt][3] * a1);
        }
    }
    __syncthreads();    // warp 0's global writes visible CTA-wide
    if (w == 1) {
        const float rf00 = (sm_m[0][gid] == -INFINITY)     ? 0.f : sm_m[0][gid];
        const float rf10 = (sm_m[1][gid] == -INFINITY)     ? 0.f : sm_m[1][gid];
        const float rf01 = (sm_m[0][gid + 8] == -INFINITY) ? 0.f : sm_m[0][gid + 8];
        const float rf11 = (sm_m[1][gid + 8] == -INFINITY) ? 0.f : sm_m[1][gid + 8];
        const float L0 = exp2f(rf00 - M0) * sm_l[0][gid]
                       + exp2f(rf10 - M0) * sm_l[1][gid];
        const float L1 = exp2f(rf01 - M1) * sm_l[0][gid + 8]
                       + exp2f(rf11 - M1) * sm_l[1][gid + 8];
        const float i0 = 1.f / L0;
        const float i1 = 1.f / L1;
        #pragma unroll
        for (int dt = 0; dt < 8; ++dt) {
            float2 u0 = *(float2*)(ob + gid * 64 + 8 * dt + 2 * qid);
            float2 u1 = *(float2*)(ob + (gid + 8) * 64 + 8 * dt + 2 * qid);
            *(float2*)(ob + gid * 64 + 8 * dt + 2 * qid) =
                make_float2((u0.x + o[dt][0] * a0) * i0,
                            (u0.y + o[dt][1] * a0) * i0);
            *(float2*)(ob + (gid + 8) * 64 + 8 * dt + 2 * qid) =
                make_float2((u1.x + o[dt][2] * a1) * i1,
                            (u1.y + o[dt][3] * a1) * i1);
        }
    }
}

extern "C" void kernel_launch(void* const* d_in, const int* in_sizes, int n_in,
                              void* d_out, int out_size) {
    const float* Q  = (const float*)d_in[0];
    const float* K  = (const float*)d_in[1];
    const float* V  = (const float*)d_in[2];
    const int*   BI = (const int*)d_in[3];
    pack_kernel<<<64, 256>>>(K, V);
    nsa16<<<TT, 64>>>(Q, BI, (float*)d_out);
}

// round 17
// speedup vs baseline: 2.2363x; 1.1095x over previous
#include <cuda_runtime.h>
#include <cuda_fp16.h>
#include <math.h>

#define TT 2048

// Fragment-ordered plain-fp16 K and V(transposed):
// [blk][nt][p][lane] -> int4 {b0(2p),b1(2p),b0(2p+1),b1(2p+1)} (fp16x2 each)
__device__ int4 g_K[32 * 8 * 2 * 32];   // 256 KB
__device__ int4 g_V[32 * 8 * 2 * 32];   // 256 KB

__device__ __forceinline__ unsigned h2u(float x, float y) {
    __half2 h = __floats2half2_rn(x, y);
    return *(unsigned*)&h;
}

__global__ void __launch_bounds__(256) pack_kernel(
    const float* __restrict__ K, const float* __restrict__ V)
{
    const int i    = blockIdx.x * 256 + threadIdx.x;   // 0..16383
    const int lane = i & 31;
    const int p    = (i >> 5) & 1;
    const int nt   = (i >> 6) & 7;
    const int blk  = i >> 9;
    const int gid  = lane >> 2, qid = lane & 3;
    const int r    = 8 * nt + gid;
    const int c0   = 32 * p + 2 * qid;
    const int c1   = c0 + 16;

    const float* Kb = K + blk * 4096;
    const float* Vb = V + blk * 4096;

    g_K[i] = make_int4(
        (int)h2u(Kb[r * 64 + c0],      Kb[r * 64 + c0 + 1]),
        (int)h2u(Kb[r * 64 + c0 + 8],  Kb[r * 64 + c0 + 9]),
        (int)h2u(Kb[r * 64 + c1],      Kb[r * 64 + c1 + 1]),
        (int)h2u(Kb[r * 64 + c1 + 8],  Kb[r * 64 + c1 + 9]));

    g_V[i] = make_int4(
        (int)h2u(Vb[c0 * 64 + r],       Vb[(c0 + 1) * 64 + r]),
        (int)h2u(Vb[(c0 + 8) * 64 + r], Vb[(c0 + 9) * 64 + r]),
        (int)h2u(Vb[c1 * 64 + r],       Vb[(c1 + 1) * 64 + r]),
        (int)h2u(Vb[(c1 + 8) * 64 + r], Vb[(c1 + 9) * 64 + r]));
}

__device__ __forceinline__ void mma16(float c[4], const int4 a, int b0, int b1) {
    asm volatile(
        "mma.sync.aligned.m16n8k16.row.col.f32.f16.f16.f32 "
        "{%0,%1,%2,%3}, {%4,%5,%6,%7}, {%8,%9}, {%0,%1,%2,%3};\n"
        : "+f"(c[0]), "+f"(c[1]), "+f"(c[2]), "+f"(c[3])
        : "r"(a.x), "r"(a.y), "r"(a.z), "r"(a.w), "r"(b0), "r"(b1));
}

__device__ __forceinline__ void cp16(int4* smem_dst, const int4* gmem_src) {
    unsigned sa = (unsigned)__cvta_generic_to_shared(smem_dst);
    asm volatile("cp.async.cg.shared.global [%0], [%1], 16;\n"
                 :: "r"(sa), "l"(gmem_src));
}
#define CP_COMMIT() asm volatile("cp.async.commit_group;\n" ::: "memory")
#define CP_WAIT2()  asm volatile("cp.async.wait_group 2;\n" ::: "memory")
#define CP_WAIT0()  asm volatile("cp.async.wait_group 0;\n" ::: "memory")

#define ONES 0x3C003C00   // fp16x2 (1.0, 1.0)

__device__ __forceinline__ int p3(int x) { return (x >= 3) ? x - 3 : x; }

// R17 = R10 byte-for-byte (one CTA per token, split-KV 2 warps, causal block
// skipping, cp.async.cg 3-slot K ring 2 halves ahead, early V LDGs, lazy-ref
// softmax, l via ones-MMA, SMEM split-softmax merge) with ONE change: the
// last valid block issues NO tail prefetch (8KB of never-read gmem traffic
// per warp-token) and drains with wait_group 0 instead.
__global__ void __launch_bounds__(64, 8) nsa17(
    const float* __restrict__ Q,   // [T,16,64]
    const int*   __restrict__ BI,  // [T,16]
    float* __restrict__ Out)       // [T,16,64]
{
    __shared__ int4  sK[2 * 3 * 256];    // 2 warps x 3 slots x 4KB
    __shared__ float sm_m[2][16];
    __shared__ float sm_l[2][16];
    __shared__ float sm_o[16 * 66];
    #define KSLOT(wi, si, ei) sK[(wi) * 768 + (si) * 256 + (ei)]

    const int t    = blockIdx.x;
    const int w    = threadIdx.x >> 5;
    const int lane = threadIdx.x & 31;
    const int gid  = lane >> 2;
    const int qid  = lane & 3;
    const int pb   = t >> 6;             // the (only possible) partial block

    // ---- Q A-fragments (scaled by 0.125*log2e), plain fp16, in regs -------
    int4 Qh[4];
    {
        const float SC = 0.18033688011112042f;   // 0.125 * log2(e)
        const float* Qp = Q + t * 1024;
        #pragma unroll
        for (int ks = 0; ks < 4; ++ks) {
            const int c0 = 16 * ks + 2 * qid;
            float2 x0 = *(const float2*)(Qp + gid * 64 + c0);
            float2 x1 = *(const float2*)(Qp + (gid + 8) * 64 + c0);
            float2 x2 = *(const float2*)(Qp + gid * 64 + c0 + 8);
            float2 x3 = *(const float2*)(Qp + (gid + 8) * 64 + c0 + 8);
            Qh[ks] = make_int4(
                (int)h2u(x0.x * SC, x0.y * SC),
                (int)h2u(x1.x * SC, x1.y * SC),
                (int)h2u(x2.x * SC, x2.y * SC),
                (int)h2u(x3.x * SC, x3.y * SC));
        }
    }

    float o[8][4];
    #pragma unroll
    for (int dt = 0; dt < 8; ++dt)
        o[dt][0] = o[dt][1] = o[dt][2] = o[dt][3] = 0.f;
    float la[4] = {0.f, 0.f, 0.f, 0.f};
    float m0 = -INFINITY, m1 = -INFINITY;
    float ref0 = 0.f, ref1 = 0.f;

    // ---- compact causally-valid block list --------------------------------
    const int* bip = BI + t * 16 + w * 8;
    int lst[8];
    int cnt = 0;
    #pragma unroll
    for (int s = 0; s < 8; ++s) {
        const int b = __ldg(bip + s);
        if (b <= pb) lst[cnt++] = b;     // b*64 <= t  <=>  b <= t>>6
    }

    if (cnt > 0) {
        // ---- preload: (lst0, half0) -> slot0, (lst0, half1) -> slot1 ------
        {
            const int4* srcb = g_K + (size_t)lst[0] * 512;
            #pragma unroll
            for (int j = 0; j < 8; ++j)
                cp16(&KSLOT(w, 0, j * 32 + lane), srcb + j * 32 + lane);
            CP_COMMIT();
            #pragma unroll
            for (int j = 0; j < 8; ++j)
                cp16(&KSLOT(w, 1, j * 32 + lane), srcb + 256 + j * 32 + lane);
            CP_COMMIT();
        }

        int cslot = 0;

        #pragma unroll 1
        for (int i = 0; i < cnt; ++i) {
            const int blkc = lst[i];
            const bool has_next = (i + 1 < cnt);
            const int nxt  = has_next ? lst[i + 1] : 0;
            const bool domask = (blkc == pb);
            const int4* Vb = g_V + (size_t)blkc * 512;
            const int4* Kn = g_K + (size_t)nxt * 512;

            float bm0 = m0, bm1 = m1;
            int4 Ph[2];

            #pragma unroll
            for (int h = 0; h < 2; ++h) {
                // -- prefetch next block's same-half K (skip on last block) -
                if (has_next) {
                    const int4* src = Kn + h * 256;
                    const int tslot = p3(cslot + 2);
                    #pragma unroll
                    for (int j = 0; j < 8; ++j)
                        cp16(&KSLOT(w, tslot, j * 32 + lane), src + j * 32 + lane);
                    CP_COMMIT();
                }
                // -- early V loads for this half ----------------------------
                int4 v[8];
                #pragma unroll
                for (int dt = 0; dt < 8; ++dt)
                    v[dt] = Vb[dt * 64 + 32 * h + lane];

                // -- wait for this half's K, then QK ------------------------
                if (has_next) { CP_WAIT2(); } else { CP_WAIT0(); }
                float sc[4][4];
                #pragma unroll
                for (int nt = 0; nt < 4; ++nt) {
                    const int4 ba = KSLOT(w, cslot, nt * 64 + lane);
                    const int4 bb = KSLOT(w, cslot, nt * 64 + 32 + lane);
                    float a[4] = {0.f, 0.f, 0.f, 0.f};
                    mma16(a, Qh[0], ba.x, ba.y);
                    mma16(a, Qh[1], ba.z, ba.w);
                    mma16(a, Qh[2], bb.x, bb.y);
                    mma16(a, Qh[3], bb.z, bb.w);
                    sc[nt][0] = a[0]; sc[nt][1] = a[1];
                    sc[nt][2] = a[2]; sc[nt][3] = a[3];
                }
                if (domask) {   // warp-uniform: only the boundary block
                    #pragma unroll
                    for (int nt = 0; nt < 4; ++nt) {
                        const int kp = blkc * 64 + 8 * (nt + 4 * h) + 2 * qid;
                        if (kp     > t) { sc[nt][0] = -INFINITY; sc[nt][2] = -INFINITY; }
                        if (kp + 1 > t) { sc[nt][1] = -INFINITY; sc[nt][3] = -INFINITY; }
                    }
                }
                #pragma unroll
                for (int nt = 0; nt < 4; ++nt) {
                    bm0 = fmaxf(bm0, fmaxf(sc[nt][0], sc[nt][1]));
                    bm1 = fmaxf(bm1, fmaxf(sc[nt][2], sc[nt][3]));
                }
                // -- exp (lazy reference) -> P A-fragments ------------------
                #pragma unroll
                for (int p = 0; p < 2; ++p) {
                    unsigned hb[4];
                    #pragma unroll
                    for (int j = 0; j < 2; ++j) {
                        const int nt = 2 * p + j;
                        __half2 e01 = h2exp2(__floats2half2_rn(sc[nt][0] - ref0,
                                                               sc[nt][1] - ref0));
                        __half2 e23 = h2exp2(__floats2half2_rn(sc[nt][2] - ref1,
                                                               sc[nt][3] - ref1));
                        hb[2 * j]     = *(unsigned*)&e01;
                        hb[2 * j + 1] = *(unsigned*)&e23;
                    }
                    Ph[p] = make_int4((int)hb[0], (int)hb[1], (int)hb[2], (int)hb[3]);
                }
                // -- PV over this half's k-steps ----------------------------
                #pragma unroll
                for (int dt = 0; dt < 8; ++dt) {
                    mma16(o[dt], Ph[0], v[dt].x, v[dt].y);
                    mma16(o[dt], Ph[1], v[dt].z, v[dt].w);
                }
                mma16(la, Ph[0], ONES, ONES);
                mma16(la, Ph[1], ONES, ONES);

                cslot = p3(cslot + 1);
            }

            // ---- block end: update max / reference, rescale ---------------
            bm0 = fmaxf(bm0, __shfl_xor_sync(0xffffffffu, bm0, 1));
            bm0 = fmaxf(bm0, __shfl_xor_sync(0xffffffffu, bm0, 2));
            bm1 = fmaxf(bm1, __shfl_xor_sync(0xffffffffu, bm1, 1));
            bm1 = fmaxf(bm1, __shfl_xor_sync(0xffffffffu, bm1, 2));
            const float nr0 = (bm0 == -INFINITY) ? 0.f : bm0;
            const float nr1 = (bm1 == -INFINITY) ? 0.f : bm1;
            const float cr0 = exp2f(ref0 - nr0);
            const float cr1 = exp2f(ref1 - nr1);
            #pragma unroll
            for (int dt = 0; dt < 8; ++dt) {
                o[dt][0] *= cr0; o[dt][1] *= cr0;
                o[dt][2] *= cr1; o[dt][3] *= cr1;
            }
            la[0] *= cr0; la[1] *= cr0; la[2] *= cr1; la[3] *= cr1;
            m0 = bm0; m1 = bm1; ref0 = nr0; ref1 = nr1;
        }
    }

    // ---- split-softmax merge ----------------------------------------------
    if (qid == 0) {
        sm_m[w][gid] = m0;  sm_m[w][gid + 8] = m1;
        sm_l[w][gid] = la[0]; sm_l[w][gid + 8] = la[2];
    }
    __syncthreads();

    const float M0 = fmaxf(sm_m[0][gid],     sm_m[1][gid]);   // finite (w0 has blk 0)
    const float M1 = fmaxf(sm_m[0][gid + 8], sm_m[1][gid + 8]);
    const float a0 = exp2f(ref0 - M0);
    const float a1 = exp2f(ref1 - M1);

    if (w == 0) {
        #pragma unroll
        for (int dt = 0; dt < 8; ++dt) {
            *(float2*)(sm_o + gid * 66 + 8 * dt + 2 * qid) =
                make_float2(o[dt][0] * a0, o[dt][1] * a0);
            *(float2*)(sm_o + (gid + 8) * 66 + 8 * dt + 2 * qid) =
                make_float2(o[dt][2] * a1, o[dt][3] * a1);
        }
    }
    __syncthreads();
    if (w == 1) {
        const float rf00 = (sm_m[0][gid] == -INFINITY)     ? 0.f : sm_m[0][gid];
        const float rf10 = (sm_m[1][gid] == -INFINITY)     ? 0.f : sm_m[1][gid];
        const float rf01 = (sm_m[0][gid + 8] == -INFINITY) ? 0.f : sm_m[0][gid + 8];
        const float rf11 = (sm_m[1][gid + 8] == -INFINITY) ? 0.f : sm_m[1][gid + 8];
        const float L0 = exp2f(rf00 - M0) * sm_l[0][gid]
                       + exp2f(rf10 - M0) * sm_l[1][gid];
        const float L1 = exp2f(rf01 - M1) * sm_l[0][gid + 8]
                       + exp2f(rf11 - M1) * sm_l[1][gid + 8];
        const float i0 = 1.f / L0;
        const float i1 = 1.f / L1;
        float* ob = Out + t * 1024;
        #pragma unroll
        for (int dt = 0; dt < 8; ++dt) {
            float2 u0 = *(float2*)(sm_o + gid * 66 + 8 * dt + 2 * qid);
            float2 u1 = *(float2*)(sm_o + (gid + 8) * 66 + 8 * dt + 2 * qid);
            *(float2*)(ob + gid * 64 + 8 * dt + 2 * qid) =
                make_float2((u0.x + o[dt][0] * a0) * i0,
                            (u0.y + o[dt][1] * a0) * i0);
            *(float2*)(ob + (gid + 8) * 64 + 8 * dt + 2 * qid) =
                make_float2((u1.x + o[dt][2] * a1) * i1,
                            (u1.y + o[dt][3] * a1) * i1);
        }
    }
}

extern "C" void kernel_launch(void* const* d_in, const int* in_sizes, int n_in,
                              void* d_out, int out_size) {
    const float* Q  = (const float*)d_in[0];
    const float* K  = (const float*)d_in[1];
    const float* V  = (const float*)d_in[2];
    const int*   BI = (const int*)d_in[3];
    pack_kernel<<<64, 256>>>(K, V);
    nsa17<<<TT, 64>>>(Q, BI, (float*)d_out);
}